// round 2
// baseline (speedup 1.0000x reference)
#include <cuda_runtime.h>
#include <cstdint>

// IWT (inverse 2x2 Haar): x (B=16, 4C=256, H=128, W=128) fp32 -> out (B, C=64, 2H, 2W)
//
// a = x[:, 0:64], b = x[:, 64:128], c = x[:, 128:192], d = x[:, 192:256]
// h00 = .5(a-b-c+d)  -> out[2h, 2w]
// h01 = .5(a+b-c-d)  -> out[2h, 2w+1]
// h10 = .5(a-b+c-d)  -> out[2h+1, 2w]
// h11 = .5(a+b+c+d)  -> out[2h+1, 2w+1]
//
// R2: touch-once streams -> __ldcs/__stcs (evict-first / streaming), and
// 8 floats per thread (2x float4 per subband) for MLP=8 front-batched loads.

#define B_  16
#define C_  64
#define H_  128
#define W_  128
#define SUBBAND_STRIDE_ (C_ * H_ * W_)   // 1048576 floats between a/b/c/d groups
#define OW_ (2 * W_)                     // 256
#define W8_ (W_ / 8)                     // 16 groups of 8 per input row

__device__ __forceinline__ float4 ldcs4(const float* p) {
    return __ldcs(reinterpret_cast<const float4*>(p));
}
__device__ __forceinline__ void stcs4(float* p, float4 v) {
    __stcs(reinterpret_cast<float4*>(p), v);
}

__global__ __launch_bounds__(256)
void iwt_kernel(const float* __restrict__ x, float* __restrict__ out) {
    // Each thread: 8 consecutive w at fixed (b, ch, h).
    // Total threads = B * C * H * W8 = 16*64*128*16 = 2,097,152
    int tid = blockIdx.x * blockDim.x + threadIdx.x;

    int w8   = tid & (W8_ - 1);          // 0..15
    int rest = tid >> 4;
    int h    = rest & (H_ - 1);          // 0..127
    rest >>= 7;
    int ch   = rest & (C_ - 1);          // 0..63
    int b    = rest >> 6;                // 0..15

    // Input base: subband 'a' plane for (b, ch), row h, col w8*8
    int in_idx = ((b * 256 + ch) * H_ + h) * W_ + (w8 << 3);

    // Front-batch all 8 loads (MLP=8)
    const float4 va0 = ldcs4(x + in_idx);
    const float4 va1 = ldcs4(x + in_idx + 4);
    const float4 vb0 = ldcs4(x + in_idx + 1 * SUBBAND_STRIDE_);
    const float4 vb1 = ldcs4(x + in_idx + 1 * SUBBAND_STRIDE_ + 4);
    const float4 vc0 = ldcs4(x + in_idx + 2 * SUBBAND_STRIDE_);
    const float4 vc1 = ldcs4(x + in_idx + 2 * SUBBAND_STRIDE_ + 4);
    const float4 vd0 = ldcs4(x + in_idx + 3 * SUBBAND_STRIDE_);
    const float4 vd1 = ldcs4(x + in_idx + 3 * SUBBAND_STRIDE_ + 4);

    const float a[8] = {va0.x, va0.y, va0.z, va0.w, va1.x, va1.y, va1.z, va1.w};
    const float bb[8] = {vb0.x, vb0.y, vb0.z, vb0.w, vb1.x, vb1.y, vb1.z, vb1.w};
    const float c[8] = {vc0.x, vc0.y, vc0.z, vc0.w, vc1.x, vc1.y, vc1.z, vc1.w};
    const float d[8] = {vd0.x, vd0.y, vd0.z, vd0.w, vd1.x, vd1.y, vd1.z, vd1.w};

    float h00[8], h01[8], h10[8], h11[8];
#pragma unroll
    for (int i = 0; i < 8; i++) {
        float apd = a[i] + d[i];
        float amd = a[i] - d[i];
        float bpc = bb[i] + c[i];
        float bmc = bb[i] - c[i];
        h00[i] = 0.5f * (amd - bmc) + d[i];   // careful: recompute exactly
        // Use the exact original expressions to keep bit behavior predictable:
        h00[i] = 0.5f * (a[i] - bb[i] - c[i] + d[i]);
        h01[i] = 0.5f * (a[i] + bb[i] - c[i] - d[i]);
        h10[i] = 0.5f * (a[i] - bb[i] + c[i] - d[i]);
        h11[i] = 0.5f * (a[i] + bb[i] + c[i] + d[i]);
        (void)apd; (void)amd; (void)bpc; (void)bmc;
    }

    // Output: rows 2h and 2h+1, 16 consecutive floats starting at 2*(w8*8)
    int out_row0 = ((b * C_ + ch) * (2 * H_) + (h << 1)) * OW_ + (w8 << 4);
    int out_row1 = out_row0 + OW_;

#pragma unroll
    for (int q = 0; q < 4; q++) {
        // pair indices 2q, 2q+1 -> interleaved (h00,h01) on even row
        stcs4(out + out_row0 + (q << 2),
              make_float4(h00[2 * q], h01[2 * q], h00[2 * q + 1], h01[2 * q + 1]));
    }
#pragma unroll
    for (int q = 0; q < 4; q++) {
        stcs4(out + out_row1 + (q << 2),
              make_float4(h10[2 * q], h11[2 * q], h10[2 * q + 1], h11[2 * q + 1]));
    }
}

extern "C" void kernel_launch(void* const* d_in, const int* in_sizes, int n_in,
                              void* d_out, int out_size) {
    const float* x = (const float*)d_in[0];
    float* out = (float*)d_out;

    const int total_threads = B_ * C_ * H_ * W8_;  // 2,097,152
    const int block = 256;
    const int grid = total_threads / block;        // 8192

    iwt_kernel<<<grid, block>>>(x, out);
}

// round 3
// speedup vs baseline: 1.1212x; 1.1212x over previous
#include <cuda_runtime.h>
#include <cstdint>

// IWT (inverse 2x2 Haar): x (B=16, 4C=256, H=128, W=128) fp32 -> out (B, C=64, 2H, 2W)
//
// a = x[:, 0:64], b = x[:, 64:128], c = x[:, 128:192], d = x[:, 192:256]
// h00 = .5(a-b-c+d)  -> out[2h, 2w]
// h01 = .5(a+b-c-d)  -> out[2h, 2w+1]
// h10 = .5(a-b+c-d)  -> out[2h+1, 2w]
// h11 = .5(a+b+c+d)  -> out[2h+1, 2w+1]
//
// R3: R1 geometry (4 floats/thread, 32 regs, occ ~78%) + streaming cache
// hints (.cs) as the ONLY delta vs R1. R2's 8-wide variant cost 12 regs and
// dropped occupancy to 48% -> regression; reverted.

#define B_  16
#define C_  64
#define H_  128
#define W_  128
#define SUBBAND_STRIDE_ (C_ * H_ * W_)  // 1048576 floats between subband groups
#define OW_ (2 * W_)                    // 256
#define WQ_ (W_ / 4)                    // 32

__device__ __forceinline__ float4 ldcs4(const float* p) {
    return __ldcs(reinterpret_cast<const float4*>(p));
}
__device__ __forceinline__ void stcs4(float* p, float4 v) {
    __stcs(reinterpret_cast<float4*>(p), v);
}

__global__ __launch_bounds__(256)
void iwt_kernel(const float* __restrict__ x, float* __restrict__ out) {
    int tid = blockIdx.x * blockDim.x + threadIdx.x;

    int w4   = tid & (WQ_ - 1);          // 0..31
    int rest = tid >> 5;
    int h    = rest & (H_ - 1);          // 0..127
    rest >>= 7;
    int ch   = rest & (C_ - 1);          // 0..63
    int b    = rest >> 6;                // 0..15

    int in_idx = ((b * 256 + ch) * H_ + h) * W_ + (w4 << 2);

    const float4 va = ldcs4(x + in_idx);
    const float4 vb = ldcs4(x + in_idx + 1 * SUBBAND_STRIDE_);
    const float4 vc = ldcs4(x + in_idx + 2 * SUBBAND_STRIDE_);
    const float4 vd = ldcs4(x + in_idx + 3 * SUBBAND_STRIDE_);

    const float a0 = va.x, a1 = va.y, a2 = va.z, a3 = va.w;
    const float b0 = vb.x, b1 = vb.y, b2 = vb.z, b3 = vb.w;
    const float c0 = vc.x, c1 = vc.y, c2 = vc.z, c3 = vc.w;
    const float d0 = vd.x, d1 = vd.y, d2 = vd.z, d3 = vd.w;

    float h00_0 = 0.5f * (a0 - b0 - c0 + d0);
    float h01_0 = 0.5f * (a0 + b0 - c0 - d0);
    float h10_0 = 0.5f * (a0 - b0 + c0 - d0);
    float h11_0 = 0.5f * (a0 + b0 + c0 + d0);

    float h00_1 = 0.5f * (a1 - b1 - c1 + d1);
    float h01_1 = 0.5f * (a1 + b1 - c1 - d1);
    float h10_1 = 0.5f * (a1 - b1 + c1 - d1);
    float h11_1 = 0.5f * (a1 + b1 + c1 + d1);

    float h00_2 = 0.5f * (a2 - b2 - c2 + d2);
    float h01_2 = 0.5f * (a2 + b2 - c2 - d2);
    float h10_2 = 0.5f * (a2 - b2 + c2 - d2);
    float h11_2 = 0.5f * (a2 + b2 + c2 + d2);

    float h00_3 = 0.5f * (a3 - b3 - c3 + d3);
    float h01_3 = 0.5f * (a3 + b3 - c3 - d3);
    float h10_3 = 0.5f * (a3 - b3 + c3 - d3);
    float h11_3 = 0.5f * (a3 + b3 + c3 + d3);

    int out_row0 = ((b * C_ + ch) * (2 * H_) + (h << 1)) * OW_ + (w4 << 3);
    int out_row1 = out_row0 + OW_;

    stcs4(out + out_row0,     make_float4(h00_0, h01_0, h00_1, h01_1));
    stcs4(out + out_row0 + 4, make_float4(h00_2, h01_2, h00_3, h01_3));
    stcs4(out + out_row1,     make_float4(h10_0, h11_0, h10_1, h11_1));
    stcs4(out + out_row1 + 4, make_float4(h10_2, h11_2, h10_3, h11_3));
}

extern "C" void kernel_launch(void* const* d_in, const int* in_sizes, int n_in,
                              void* d_out, int out_size) {
    const float* x = (const float*)d_in[0];
    float* out = (float*)d_out;

    const int total_threads = B_ * C_ * H_ * WQ_;  // 4,194,304
    const int block = 256;
    const int grid = total_threads / block;        // 16384

    iwt_kernel<<<grid, block>>>(x, out);
}

// round 4
// speedup vs baseline: 1.1549x; 1.0300x over previous
#include <cuda_runtime.h>
#include <cstdint>

// IWT (inverse 2x2 Haar): x (B=16, 4C=256, H=128, W=128) fp32 -> out (B, C=64, 2H, 2W)
//
// h00 = .5(a-b-c+d) -> out[2h,2w]    h01 = .5(a+b-c-d) -> out[2h,2w+1]
// h10 = .5(a-b+c-d) -> out[2h+1,2w]  h11 = .5(a+b+c+d) -> out[2h+1,2w+1]
//
// R4: R1 geometry (4 floats/thread, 4x LDG.128, occ ~78%) but the two
// adjacent float4 stores per output row fused into one 256-bit
// st.global.v8.f32 (sm_100+). Halves STG instruction count (issue cost
// 12cyc/STG.128) without raising register pressure on the load side.

#define B_  16
#define C_  64
#define H_  128
#define W_  128
#define SUBBAND_STRIDE_ (C_ * H_ * W_)  // 1048576 floats between subband groups
#define OW_ (2 * W_)                    // 256
#define WQ_ (W_ / 4)                    // 32

__device__ __forceinline__ void stg256(float* p,
                                       float v0, float v1, float v2, float v3,
                                       float v4, float v5, float v6, float v7) {
#if defined(__CUDA_ARCH__) && (__CUDA_ARCH__ >= 1000)
    asm volatile(
        "st.global.v8.f32 [%0], {%1, %2, %3, %4, %5, %6, %7, %8};"
        :: "l"(p), "f"(v0), "f"(v1), "f"(v2), "f"(v3),
           "f"(v4), "f"(v5), "f"(v6), "f"(v7)
        : "memory");
#else
    float4* q = reinterpret_cast<float4*>(p);
    q[0] = make_float4(v0, v1, v2, v3);
    q[1] = make_float4(v4, v5, v6, v7);
#endif
}

__global__ __launch_bounds__(256)
void iwt_kernel(const float* __restrict__ x, float* __restrict__ out) {
    int tid = blockIdx.x * blockDim.x + threadIdx.x;

    int w4   = tid & (WQ_ - 1);          // 0..31
    int rest = tid >> 5;
    int h    = rest & (H_ - 1);          // 0..127
    rest >>= 7;
    int ch   = rest & (C_ - 1);          // 0..63
    int b    = rest >> 6;                // 0..15

    int in_idx = ((b * 256 + ch) * H_ + h) * W_ + (w4 << 2);

    const float4 va = *reinterpret_cast<const float4*>(x + in_idx);
    const float4 vb = *reinterpret_cast<const float4*>(x + in_idx + 1 * SUBBAND_STRIDE_);
    const float4 vc = *reinterpret_cast<const float4*>(x + in_idx + 2 * SUBBAND_STRIDE_);
    const float4 vd = *reinterpret_cast<const float4*>(x + in_idx + 3 * SUBBAND_STRIDE_);

    const float a0 = va.x, a1 = va.y, a2 = va.z, a3 = va.w;
    const float b0 = vb.x, b1 = vb.y, b2 = vb.z, b3 = vb.w;
    const float c0 = vc.x, c1 = vc.y, c2 = vc.z, c3 = vc.w;
    const float d0 = vd.x, d1 = vd.y, d2 = vd.z, d3 = vd.w;

    float h00_0 = 0.5f * (a0 - b0 - c0 + d0);
    float h01_0 = 0.5f * (a0 + b0 - c0 - d0);
    float h10_0 = 0.5f * (a0 - b0 + c0 - d0);
    float h11_0 = 0.5f * (a0 + b0 + c0 + d0);

    float h00_1 = 0.5f * (a1 - b1 - c1 + d1);
    float h01_1 = 0.5f * (a1 + b1 - c1 - d1);
    float h10_1 = 0.5f * (a1 - b1 + c1 - d1);
    float h11_1 = 0.5f * (a1 + b1 + c1 + d1);

    float h00_2 = 0.5f * (a2 - b2 - c2 + d2);
    float h01_2 = 0.5f * (a2 + b2 - c2 - d2);
    float h10_2 = 0.5f * (a2 - b2 + c2 - d2);
    float h11_2 = 0.5f * (a2 + b2 + c2 + d2);

    float h00_3 = 0.5f * (a3 - b3 - c3 + d3);
    float h01_3 = 0.5f * (a3 + b3 - c3 - d3);
    float h10_3 = 0.5f * (a3 - b3 + c3 - d3);
    float h11_3 = 0.5f * (a3 + b3 + c3 + d3);

    int out_row0 = ((b * C_ + ch) * (2 * H_) + (h << 1)) * OW_ + (w4 << 3);
    int out_row1 = out_row0 + OW_;

    // Even output row: [h00_0 h01_0 h00_1 h01_1 h00_2 h01_2 h00_3 h01_3]
    stg256(out + out_row0,
           h00_0, h01_0, h00_1, h01_1, h00_2, h01_2, h00_3, h01_3);
    // Odd output row: [h10_0 h11_0 h10_1 h11_1 h10_2 h11_2 h10_3 h11_3]
    stg256(out + out_row1,
           h10_0, h11_0, h10_1, h11_1, h10_2, h11_2, h10_3, h11_3);
}

extern "C" void kernel_launch(void* const* d_in, const int* in_sizes, int n_in,
                              void* d_out, int out_size) {
    const float* x = (const float*)d_in[0];
    float* out = (float*)d_out;

    const int total_threads = B_ * C_ * H_ * WQ_;  // 4,194,304
    const int block = 256;
    const int grid = total_threads / block;        // 16384

    iwt_kernel<<<grid, block>>>(x, out);
}